// round 15
// baseline (speedup 1.0000x reference)
#include <cuda_runtime.h>
#include <cstdint>

// Problem shape (fixed for this dataset entry)
#define B_    2
#define N_    50000
#define C_    64
#define M_    50000
#define K_    16
#define H_    8
#define CMID_ 16

// Runtime-detected index width flag (int64 vs int32), set by detect kernel.
__device__ int g_idx_is64;

__global__ void detect_idx_kernel(const unsigned int* __restrict__ w) {
    if (threadIdx.x == 0 && blockIdx.x == 0) {
        int is64 = 1;
        #pragma unroll 1
        for (int i = 0; i < 256; i++) {
            if (w[2 * i + 1] != 0u) { is64 = 0; break; }
        }
        g_idx_is64 = is64;
    }
}

// TWO points per WARP (broadcast amortization); 4 warps -> 8 points per CTA.
// Lane: pt = lane>>4 selects the point, q = lane&15 owns 4 contiguous
// channels [4q,4q+4) (= one guidance head, hd=q>>1) and ALL 16 w.
// Per k per warp:
//   1 LDG.128 gather  (zero-dup: each half-warp covers its point's 256B row)
//   4 LDS.128 W       (2 distinct addrs; uniform per quarter-warp; serves BOTH
//                      points -> the dominant broadcast cost is halved per pt)
//   1 LDS guid (16 distinct words; sgd stride padded to 136 to dodge the
//               pt0/pt1 bank overlap) + 1 LDS idx
//   4 FMUL + 4 dup movs + 32 fma.rn.f32x2
// acc packs along w: acc[c_local*8+wp] = {out[4q+c_local][2wp], ..[2wp+1]},
// so W pairs from LDS.128 are multiplicands DIRECTLY (no dup movs on W).
// Epilogue: swizzled smem bounce (slot (i+q)&15, conflict-free per
// quarter-warp) -> 8KB contiguous flush, all STG.128 coalesced (__stcs).
__global__ void __launch_bounds__(128, 5)
pcf_kernel(const float* __restrict__ feat,
           const void*  __restrict__ inds_raw,
           const float* __restrict__ guid,
           const float* __restrict__ wn,
           float* __restrict__ out)
{
    // Per-warp 8KB blob:
    //  phase 1 (k-loop): [0,512) wn (pt-major 2x256), [512,784) guid (2x136)
    //  phase 2 (epilogue): whole 2048 floats = output bounce (2 pts x 1024)
    __shared__ __align__(16) float sblob[4][2048];
    __shared__ int sidx[4][32];

    const int wid  = threadIdx.x >> 5;
    const int lane = threadIdx.x & 31;
    const int pair = blockIdx.x * 4 + wid;      // point-pair id in [0, B*M/2)
    const int pt   = lane >> 4;                 // which point of the pair
    const int q    = lane & 15;                 // channel quad [4q, 4q+4)
    const int p    = pair * 2 + pt;
    const int b    = (p >= M_) ? 1 : 0;
    const int hd   = q >> 1;                    // guidance head of those 4 ch

    float* swn = sblob[wid];                    // 512 floats (2 pts x 256)
    float* sgd = sblob[wid] + 512;              // 2 x 136 (padded stride)
    float* sou = sblob[wid];                    // 2048 floats (reused)

    // ---- per-warp staging: wn (2KB), guid (1KB), 32 indices ----
    {
        const float4* wsrc = (const float4*)(wn + (size_t)pair * 512);
        float4* wdst = (float4*)swn;
        #pragma unroll
        for (int r = 0; r < 4; r++)
            wdst[lane + r * 32] = __ldcs(wsrc + lane + r * 32);

        const float4* gsrc = (const float4*)(guid + (size_t)pair * 256);
        #pragma unroll
        for (int r = 0; r < 2; r++) {
            const int g   = lane + r * 32;      // 0..63 (32 float4 per point)
            const int gpt = g >> 5;
            const int off = g & 31;
            *(float4*)(sgd + gpt * 136 + off * 4) = __ldcs(gsrc + g);
        }
        long long idx;
        const size_t off = (size_t)pair * 32 + lane;
        if (g_idx_is64) idx = ((const long long*)inds_raw)[off];
        else            idx = (long long)((const int*)inds_raw)[off];
        sidx[wid][lane] = (int)idx;
    }
    __syncwarp();

    const float* fb     = feat + (size_t)b * ((size_t)N_ * C_) + 4 * q;
    const float* mysgd  = sgd + pt * 136;
    const float* mywn   = swn + pt * 256;
    const int*   myidx  = sidx[wid] + pt * K_;

    unsigned long long acc[32];
    #pragma unroll
    for (int i = 0; i < 32; i++) acc[i] = 0ull;

    // depth-1 double buffer on the gather (one LDG.128 in flight)
    ulonglong2 A = *(const ulonglong2*)(fb + (size_t)myidx[0] * C_);

    #pragma unroll 4
    for (int k = 0; k < K_; k++) {
        const ulonglong2 cur = A;
        if (k + 1 < K_)
            A = *(const ulonglong2*)(fb + (size_t)myidx[k + 1] * C_);

        const float g = mysgd[k * H_ + hd];
        const float2 f01 = *(const float2*)&cur.x;
        const float2 f23 = *(const float2*)&cur.y;
        const float m0 = f01.x * g, m1 = f01.y * g;
        const float m2 = f23.x * g, m3 = f23.y * g;
        unsigned long long d0, d1, d2, d3;
        asm("mov.b64 %0, {%1, %1};" : "=l"(d0) : "f"(m0));
        asm("mov.b64 %0, {%1, %1};" : "=l"(d1) : "f"(m1));
        asm("mov.b64 %0, {%1, %1};" : "=l"(d2) : "f"(m2));
        asm("mov.b64 %0, {%1, %1};" : "=l"(d3) : "f"(m3));

        const ulonglong2* wr = (const ulonglong2*)(mywn + k * CMID_);
        // first half: w-pairs 0..3
        {
            const ulonglong2 Wa = wr[0];   // wp0, wp1
            const ulonglong2 Wb = wr[1];   // wp2, wp3
            asm("fma.rn.f32x2 %0, %1, %2, %3;" : "=l"(acc[ 0]) : "l"(d0), "l"(Wa.x), "l"(acc[ 0]));
            asm("fma.rn.f32x2 %0, %1, %2, %3;" : "=l"(acc[ 1]) : "l"(d0), "l"(Wa.y), "l"(acc[ 1]));
            asm("fma.rn.f32x2 %0, %1, %2, %3;" : "=l"(acc[ 2]) : "l"(d0), "l"(Wb.x), "l"(acc[ 2]));
            asm("fma.rn.f32x2 %0, %1, %2, %3;" : "=l"(acc[ 3]) : "l"(d0), "l"(Wb.y), "l"(acc[ 3]));
            asm("fma.rn.f32x2 %0, %1, %2, %3;" : "=l"(acc[ 8]) : "l"(d1), "l"(Wa.x), "l"(acc[ 8]));
            asm("fma.rn.f32x2 %0, %1, %2, %3;" : "=l"(acc[ 9]) : "l"(d1), "l"(Wa.y), "l"(acc[ 9]));
            asm("fma.rn.f32x2 %0, %1, %2, %3;" : "=l"(acc[10]) : "l"(d1), "l"(Wb.x), "l"(acc[10]));
            asm("fma.rn.f32x2 %0, %1, %2, %3;" : "=l"(acc[11]) : "l"(d1), "l"(Wb.y), "l"(acc[11]));
            asm("fma.rn.f32x2 %0, %1, %2, %3;" : "=l"(acc[16]) : "l"(d2), "l"(Wa.x), "l"(acc[16]));
            asm("fma.rn.f32x2 %0, %1, %2, %3;" : "=l"(acc[17]) : "l"(d2), "l"(Wa.y), "l"(acc[17]));
            asm("fma.rn.f32x2 %0, %1, %2, %3;" : "=l"(acc[18]) : "l"(d2), "l"(Wb.x), "l"(acc[18]));
            asm("fma.rn.f32x2 %0, %1, %2, %3;" : "=l"(acc[19]) : "l"(d2), "l"(Wb.y), "l"(acc[19]));
            asm("fma.rn.f32x2 %0, %1, %2, %3;" : "=l"(acc[24]) : "l"(d3), "l"(Wa.x), "l"(acc[24]));
            asm("fma.rn.f32x2 %0, %1, %2, %3;" : "=l"(acc[25]) : "l"(d3), "l"(Wa.y), "l"(acc[25]));
            asm("fma.rn.f32x2 %0, %1, %2, %3;" : "=l"(acc[26]) : "l"(d3), "l"(Wb.x), "l"(acc[26]));
            asm("fma.rn.f32x2 %0, %1, %2, %3;" : "=l"(acc[27]) : "l"(d3), "l"(Wb.y), "l"(acc[27]));
        }
        // second half: w-pairs 4..7
        {
            const ulonglong2 Wc = wr[2];   // wp4, wp5
            const ulonglong2 Wd = wr[3];   // wp6, wp7
            asm("fma.rn.f32x2 %0, %1, %2, %3;" : "=l"(acc[ 4]) : "l"(d0), "l"(Wc.x), "l"(acc[ 4]));
            asm("fma.rn.f32x2 %0, %1, %2, %3;" : "=l"(acc[ 5]) : "l"(d0), "l"(Wc.y), "l"(acc[ 5]));
            asm("fma.rn.f32x2 %0, %1, %2, %3;" : "=l"(acc[ 6]) : "l"(d0), "l"(Wd.x), "l"(acc[ 6]));
            asm("fma.rn.f32x2 %0, %1, %2, %3;" : "=l"(acc[ 7]) : "l"(d0), "l"(Wd.y), "l"(acc[ 7]));
            asm("fma.rn.f32x2 %0, %1, %2, %3;" : "=l"(acc[12]) : "l"(d1), "l"(Wc.x), "l"(acc[12]));
            asm("fma.rn.f32x2 %0, %1, %2, %3;" : "=l"(acc[13]) : "l"(d1), "l"(Wc.y), "l"(acc[13]));
            asm("fma.rn.f32x2 %0, %1, %2, %3;" : "=l"(acc[14]) : "l"(d1), "l"(Wd.x), "l"(acc[14]));
            asm("fma.rn.f32x2 %0, %1, %2, %3;" : "=l"(acc[15]) : "l"(d1), "l"(Wd.y), "l"(acc[15]));
            asm("fma.rn.f32x2 %0, %1, %2, %3;" : "=l"(acc[20]) : "l"(d2), "l"(Wc.x), "l"(acc[20]));
            asm("fma.rn.f32x2 %0, %1, %2, %3;" : "=l"(acc[21]) : "l"(d2), "l"(Wc.y), "l"(acc[21]));
            asm("fma.rn.f32x2 %0, %1, %2, %3;" : "=l"(acc[22]) : "l"(d2), "l"(Wd.x), "l"(acc[22]));
            asm("fma.rn.f32x2 %0, %1, %2, %3;" : "=l"(acc[23]) : "l"(d2), "l"(Wd.y), "l"(acc[23]));
            asm("fma.rn.f32x2 %0, %1, %2, %3;" : "=l"(acc[28]) : "l"(d3), "l"(Wc.x), "l"(acc[28]));
            asm("fma.rn.f32x2 %0, %1, %2, %3;" : "=l"(acc[29]) : "l"(d3), "l"(Wc.y), "l"(acc[29]));
            asm("fma.rn.f32x2 %0, %1, %2, %3;" : "=l"(acc[30]) : "l"(d3), "l"(Wd.x), "l"(acc[30]));
            asm("fma.rn.f32x2 %0, %1, %2, %3;" : "=l"(acc[31]) : "l"(d3), "l"(Wd.y), "l"(acc[31]));
        }
    }
    __syncwarp();   // done reading swn/sgd before the bounce reuses the blob

    // ---- epilogue: swizzled bounce. Lane region: pt*1024 + q*64 floats.
    // Chunk i = c_local*4 + jq holds out[4q+c_local][4jq..4jq+4) =
    // {acc[c_local*8+2jq], acc[c_local*8+2jq+1]}; stored at slot (i+q)&15.
    // Per quarter-warp all slot&7 distinct -> conflict-free.
    {
        float* sb = sou + pt * 1024 + q * 64;
        #pragma unroll
        for (int i = 0; i < 16; i++) {
            const int r  = i >> 2;               // c_local
            const int jq = i & 3;                // w quad
            const int s  = (i + q) & 15;         // swizzled slot
            *(ulonglong2*)(sb + s * 4) =
                make_ulonglong2(acc[r * 8 + 2 * jq], acc[r * 8 + 2 * jq + 1]);
        }
    }
    __syncwarp();
    // Coalesced flush of both points (2048 floats): flat = j*128 + lane*4.
    // Source: pt' = flat>>10; rem = flat&1023; c = rem>>4; w = rem&15;
    // q' = c>>2; i = (c&3)*4 + (w>>2); slot = (i+q')&15. Conflict-free.
    {
        float* o = out + (size_t)pair * 2048;
        #pragma unroll
        for (int j = 0; j < 16; j++) {
            const int flat = j * 128 + lane * 4;
            const int fpt  = flat >> 10;
            const int rem  = flat & 1023;
            const int c    = rem >> 4;
            const int w    = rem & 15;
            const int qq   = c >> 2;
            const int i    = (c & 3) * 4 + (w >> 2);
            const int s    = (i + qq) & 15;
            const float4 v = *(const float4*)(sou + fpt * 1024 + qq * 64 + s * 4);
            __stcs((float4*)(o + flat), v);
        }
    }
}

extern "C" void kernel_launch(void* const* d_in, const int* in_sizes, int n_in,
                              void* d_out, int out_size) {
    const float* feat = (const float*)d_in[0];
    const void*  inds = d_in[1];
    const float* guid = (const float*)d_in[2];
    const float* wn   = (const float*)d_in[3];
    float* out = (float*)d_out;

    detect_idx_kernel<<<1, 32>>>((const unsigned int*)inds);
    pcf_kernel<<<(B_ * M_) / 8, 128>>>(feat, inds, guid, wn, out);
}